// round 1
// baseline (speedup 1.0000x reference)
#include <cuda_runtime.h>

// SingleSelfHeadAttention: b=4, s=2048, d=1024, fp32, causal.
// Decomposition:
//   1) Q = x@Wq + bq ; K = x@Wk + bk ; V = x@Wv + bv     (sgemm_nn_bias, M=8192)
//   2) S = Q @ K^T * 1/32 (per batch, lower-triangle blocks only)
//   3) row softmax with causal mask (in-place on S), zero-pad diag-block tail
//   4) AO = P @ V (per batch, K-loop bounded by causal block row)
//   5) out = AO @ Wo + bo
// All scratch in __device__ globals (no allocation).

#define BM 128
#define BN 128
#define BK 8
#define TM 8
#define TN 8
#define NTHREADS 256

static constexpr int Bn = 4;
static constexpr int Sq = 2048;
static constexpr int Dd = 1024;
static constexpr int Mm = Bn * Sq;   // 8192

__device__ float g_Q[(size_t)Mm * Dd];
__device__ float g_K[(size_t)Mm * Dd];
__device__ float g_V[(size_t)Mm * Dd];
__device__ float g_AO[(size_t)Mm * Dd];
__device__ float g_S[(size_t)Bn * Sq * Sq];   // 64 MB score/prob scratch

// ---------------------------------------------------------------------------
// NN GEMM with optional bias: C[M,N] = A[M,K] @ B[K,N] (+ bias[N])
// 128x128 block tile, BK=8, 8x8 per-thread tile, 256 threads.
// All dims assumed multiples of the tile sizes (true for this problem).
// ---------------------------------------------------------------------------
__global__ __launch_bounds__(NTHREADS)
void sgemm_nn_bias(const float* __restrict__ A, const float* __restrict__ B,
                   const float* __restrict__ bias, float* __restrict__ C,
                   int M, int N, int K)
{
    __shared__ float As[BK][BM];
    __shared__ float Bs[BK][BN];

    const int bi = blockIdx.y, bj = blockIdx.x;
    const int tid = threadIdx.x;
    const int tr = tid >> 4;        // 0..15
    const int tc = tid & 15;        // 0..15

    const int aRow = tid >> 1;           // 0..127
    const int aCol = (tid & 1) << 2;     // 0 or 4
    const int bRow = tid >> 5;           // 0..7
    const int bCol = (tid & 31) << 2;    // 0..124

    const float* Ab = A + (size_t)(bi * BM) * K;
    const float* Bb = B + bj * BN;

    float acc[TM][TN] = {};

    for (int k0 = 0; k0 < K; k0 += BK) {
        float4 a4 = *(const float4*)(Ab + (size_t)aRow * K + k0 + aCol);
        As[aCol + 0][aRow] = a4.x;
        As[aCol + 1][aRow] = a4.y;
        As[aCol + 2][aRow] = a4.z;
        As[aCol + 3][aRow] = a4.w;
        float4 b4 = *(const float4*)(Bb + (size_t)(k0 + bRow) * N + bCol);
        *(float4*)&Bs[bRow][bCol] = b4;
        __syncthreads();

        #pragma unroll
        for (int kk = 0; kk < BK; kk++) {
            float ar[TM], br[TN];
            #pragma unroll
            for (int i = 0; i < TM; i++) ar[i] = As[kk][tr * TM + i];
            #pragma unroll
            for (int j = 0; j < TN; j++) br[j] = Bs[kk][tc * TN + j];
            #pragma unroll
            for (int i = 0; i < TM; i++)
                #pragma unroll
                for (int j = 0; j < TN; j++)
                    acc[i][j] = fmaf(ar[i], br[j], acc[i][j]);
        }
        __syncthreads();
    }

    float* Cb = C + (size_t)(bi * BM) * N + bj * BN;
    #pragma unroll
    for (int i = 0; i < TM; i++) {
        const int row = tr * TM + i;
        #pragma unroll
        for (int j = 0; j < TN; j += 4) {
            const int col = tc * TN + j;
            float4 o;
            o.x = acc[i][j + 0];
            o.y = acc[i][j + 1];
            o.z = acc[i][j + 2];
            o.w = acc[i][j + 3];
            if (bias) {
                o.x += bias[bj * BN + col + 0];
                o.y += bias[bj * BN + col + 1];
                o.z += bias[bj * BN + col + 2];
                o.w += bias[bj * BN + col + 3];
            }
            *(float4*)(Cb + (size_t)row * N + col) = o;
        }
    }
}

// ---------------------------------------------------------------------------
// Scores: S[z, i, j] = scale * dot(Q[z,i,:], K[z,j,:]).  A@B^T form.
// Skips blocks strictly above the block diagonal (causal).
// ---------------------------------------------------------------------------
__global__ __launch_bounds__(NTHREADS)
void sgemm_nt_scores(const float* __restrict__ Q, const float* __restrict__ Km,
                     float* __restrict__ Sout, float scale)
{
    if (blockIdx.x > blockIdx.y) return;   // strictly above diagonal: never read

    __shared__ float As[BK][BM];
    __shared__ float Bs[BK][BN];

    const int bi = blockIdx.y, bj = blockIdx.x, z = blockIdx.z;
    const int tid = threadIdx.x;
    const int tr = tid >> 4;
    const int tc = tid & 15;

    const int aRow = tid >> 1;
    const int aCol = (tid & 1) << 2;

    const float* Ab = Q  + (size_t)z * Sq * Dd + (size_t)(bi * BM) * Dd;
    const float* Bb = Km + (size_t)z * Sq * Dd + (size_t)(bj * BN) * Dd;

    float acc[TM][TN] = {};

    for (int k0 = 0; k0 < Dd; k0 += BK) {
        float4 a4 = *(const float4*)(Ab + (size_t)aRow * Dd + k0 + aCol);
        As[aCol + 0][aRow] = a4.x;
        As[aCol + 1][aRow] = a4.y;
        As[aCol + 2][aRow] = a4.z;
        As[aCol + 3][aRow] = a4.w;
        float4 b4 = *(const float4*)(Bb + (size_t)aRow * Dd + k0 + aCol);
        Bs[aCol + 0][aRow] = b4.x;
        Bs[aCol + 1][aRow] = b4.y;
        Bs[aCol + 2][aRow] = b4.z;
        Bs[aCol + 3][aRow] = b4.w;
        __syncthreads();

        #pragma unroll
        for (int kk = 0; kk < BK; kk++) {
            float ar[TM], br[TN];
            #pragma unroll
            for (int i = 0; i < TM; i++) ar[i] = As[kk][tr * TM + i];
            #pragma unroll
            for (int j = 0; j < TN; j++) br[j] = Bs[kk][tc * TN + j];
            #pragma unroll
            for (int i = 0; i < TM; i++)
                #pragma unroll
                for (int j = 0; j < TN; j++)
                    acc[i][j] = fmaf(ar[i], br[j], acc[i][j]);
        }
        __syncthreads();
    }

    float* Cb = Sout + (size_t)z * Sq * Sq + (size_t)(bi * BM) * Sq + bj * BN;
    #pragma unroll
    for (int i = 0; i < TM; i++) {
        const int row = tr * TM + i;
        #pragma unroll
        for (int j = 0; j < TN; j += 4) {
            const int col = tc * TN + j;
            float4 o;
            o.x = acc[i][j + 0] * scale;
            o.y = acc[i][j + 1] * scale;
            o.z = acc[i][j + 2] * scale;
            o.w = acc[i][j + 3] * scale;
            *(float4*)(Cb + (size_t)row * Sq + col) = o;
        }
    }
}

// ---------------------------------------------------------------------------
// Causal row softmax, in place on S. One block per (batch,query) row.
// Normalizes over j in [0, q]; zeros j in (q, end-of-diagonal-128-block).
// ---------------------------------------------------------------------------
__global__ __launch_bounds__(NTHREADS)
void softmax_causal(float* __restrict__ Sm)
{
    const int gq = blockIdx.x;                 // 0 .. Bn*Sq-1
    const int q  = gq & (Sq - 1);
    float* row = Sm + (size_t)gq * Sq;
    const int len = q + 1;
    const int tid = threadIdx.x;

    __shared__ float red[NTHREADS];

    float m = -1e30f;
    for (int j = tid; j < len; j += NTHREADS) m = fmaxf(m, row[j]);
    red[tid] = m;
    __syncthreads();
    for (int s = NTHREADS / 2; s > 0; s >>= 1) {
        if (tid < s) red[tid] = fmaxf(red[tid], red[tid + s]);
        __syncthreads();
    }
    m = red[0];
    __syncthreads();

    float sum = 0.f;
    for (int j = tid; j < len; j += NTHREADS) {
        float e = __expf(row[j] - m);
        row[j] = e;
        sum += e;
    }
    red[tid] = sum;
    __syncthreads();
    for (int s = NTHREADS / 2; s > 0; s >>= 1) {
        if (tid < s) red[tid] += red[tid + s];
        __syncthreads();
    }
    const float inv = 1.0f / red[0];

    for (int j = tid; j < len; j += NTHREADS) row[j] *= inv;

    // zero tail of the diagonal 128-block so the PV GEMM can read full tiles
    const int jend = ((q >> 7) + 1) << 7;
    for (int j = len + tid; j < jend; j += NTHREADS) row[j] = 0.f;
}

// ---------------------------------------------------------------------------
// PV: AO[z,i,:] = sum_k P[z,i,k] * V[z,k,:].  NN GEMM, K bounded causally.
// ---------------------------------------------------------------------------
__global__ __launch_bounds__(NTHREADS)
void sgemm_pv(const float* __restrict__ P, const float* __restrict__ V,
              float* __restrict__ O)
{
    __shared__ float As[BK][BM];
    __shared__ float Bs[BK][BN];

    const int bi = blockIdx.y, bj = blockIdx.x, z = blockIdx.z;
    const int tid = threadIdx.x;
    const int tr = tid >> 4;
    const int tc = tid & 15;

    const int aRow = tid >> 1;
    const int aCol = (tid & 1) << 2;
    const int bRow = tid >> 5;
    const int bCol = (tid & 31) << 2;

    const float* Ab = P + (size_t)z * Sq * Sq + (size_t)(bi * BM) * Sq;
    const float* Bb = V + (size_t)z * Sq * Dd + bj * BN;

    const int kmax = (bi + 1) * BM;   // causal bound, multiple of BK

    float acc[TM][TN] = {};

    for (int k0 = 0; k0 < kmax; k0 += BK) {
        float4 a4 = *(const float4*)(Ab + (size_t)aRow * Sq + k0 + aCol);
        As[aCol + 0][aRow] = a4.x;
        As[aCol + 1][aRow] = a4.y;
        As[aCol + 2][aRow] = a4.z;
        As[aCol + 3][aRow] = a4.w;
        float4 b4 = *(const float4*)(Bb + (size_t)(k0 + bRow) * Dd + bCol);
        *(float4*)&Bs[bRow][bCol] = b4;
        __syncthreads();

        #pragma unroll
        for (int kk = 0; kk < BK; kk++) {
            float ar[TM], br[TN];
            #pragma unroll
            for (int i = 0; i < TM; i++) ar[i] = As[kk][tr * TM + i];
            #pragma unroll
            for (int j = 0; j < TN; j++) br[j] = Bs[kk][tc * TN + j];
            #pragma unroll
            for (int i = 0; i < TM; i++)
                #pragma unroll
                for (int j = 0; j < TN; j++)
                    acc[i][j] = fmaf(ar[i], br[j], acc[i][j]);
        }
        __syncthreads();
    }

    float* Cb = O + (size_t)z * Sq * Dd + (size_t)(bi * BM) * Dd + bj * BN;
    #pragma unroll
    for (int i = 0; i < TM; i++) {
        const int row = tr * TM + i;
        #pragma unroll
        for (int j = 0; j < TN; j += 4) {
            const int col = tc * TN + j;
            float4 o;
            o.x = acc[i][j + 0];
            o.y = acc[i][j + 1];
            o.z = acc[i][j + 2];
            o.w = acc[i][j + 3];
            *(float4*)(Cb + (size_t)row * Dd + col) = o;
        }
    }
}

// ---------------------------------------------------------------------------
extern "C" void kernel_launch(void* const* d_in, const int* in_sizes, int n_in,
                              void* d_out, int out_size)
{
    const float* x  = (const float*)d_in[0];
    const float* Wq = (const float*)d_in[1];
    const float* bq = (const float*)d_in[2];
    const float* Wk = (const float*)d_in[3];
    const float* bk = (const float*)d_in[4];
    const float* Wv = (const float*)d_in[5];
    const float* bv = (const float*)d_in[6];
    const float* Wo = (const float*)d_in[7];
    const float* bo = (const float*)d_in[8];
    float* out = (float*)d_out;

    float *Qp, *Kp, *Vp, *AOp, *Sp;
    cudaGetSymbolAddress((void**)&Qp,  g_Q);
    cudaGetSymbolAddress((void**)&Kp,  g_K);
    cudaGetSymbolAddress((void**)&Vp,  g_V);
    cudaGetSymbolAddress((void**)&AOp, g_AO);
    cudaGetSymbolAddress((void**)&Sp,  g_S);

    const float scale = 1.0f / 32.0f;   // 1/sqrt(1024)

    dim3 gProj(Dd / BN, Mm / BM);                 // 8 x 64
    sgemm_nn_bias<<<gProj, NTHREADS>>>(x, Wq, bq, Qp, Mm, Dd, Dd);
    sgemm_nn_bias<<<gProj, NTHREADS>>>(x, Wk, bk, Kp, Mm, Dd, Dd);
    sgemm_nn_bias<<<gProj, NTHREADS>>>(x, Wv, bv, Vp, Mm, Dd, Dd);

    dim3 gScores(Sq / BN, Sq / BM, Bn);           // 16 x 16 x 4
    sgemm_nt_scores<<<gScores, NTHREADS>>>(Qp, Kp, Sp, scale);

    softmax_causal<<<Mm, NTHREADS>>>(Sp);

    dim3 gPV(Dd / BN, Sq / BM, Bn);               // 8 x 16 x 4
    sgemm_pv<<<gPV, NTHREADS>>>(Sp, Vp, AOp);

    sgemm_nn_bias<<<gProj, NTHREADS>>>(AOp, Wo, bo, out, Mm, Dd, Dd);
}

// round 3
// speedup vs baseline: 2.9467x; 2.9467x over previous
#include <cuda_runtime.h>
#include <cuda_bf16.h>
#include <cstdint>

// SingleSelfHeadAttention b=4, s=2048, d=1024, causal, fp32 I/O.
// All GEMMs via mma.sync.m16n8k16 bf16 (HMMA), bf16x3 hi/lo emulated fp32.

static constexpr int Bn = 4;
static constexpr int Sq = 2048;
static constexpr int Dd = 1024;
static constexpr int Mm = Bn * Sq;          // 8192

// ---------------- device scratch ----------------
__device__ __nv_bfloat16 g_xh[(size_t)Mm * Dd],  g_xl[(size_t)Mm * Dd];
__device__ __nv_bfloat16 g_wqh[(size_t)Dd * Dd], g_wql[(size_t)Dd * Dd];
__device__ __nv_bfloat16 g_wkh[(size_t)Dd * Dd], g_wkl[(size_t)Dd * Dd];
__device__ __nv_bfloat16 g_wvh[(size_t)Dd * Dd], g_wvl[(size_t)Dd * Dd];
__device__ __nv_bfloat16 g_woh[(size_t)Dd * Dd], g_wol[(size_t)Dd * Dd];
__device__ __nv_bfloat16 g_qh[(size_t)Mm * Dd],  g_ql[(size_t)Mm * Dd];
__device__ __nv_bfloat16 g_kh[(size_t)Mm * Dd],  g_kl[(size_t)Mm * Dd];
__device__ __nv_bfloat16 g_vth[(size_t)Bn * Dd * Sq], g_vtl[(size_t)Bn * Dd * Sq];
__device__ float         g_S [(size_t)Bn * Sq * Sq];
__device__ __nv_bfloat16 g_ph[(size_t)Bn * Sq * Sq], g_pl[(size_t)Bn * Sq * Sq];
__device__ __nv_bfloat16 g_aoh[(size_t)Mm * Dd], g_aol[(size_t)Mm * Dd];

// ---------------- PTX helpers ----------------
__device__ __forceinline__ uint32_t smem_u32(const void* p) {
    uint32_t a;
    asm("{ .reg .u64 t; cvta.to.shared.u64 t, %1; cvt.u32.u64 %0, t; }" : "=r"(a) : "l"(p));
    return a;
}
#define CP_ASYNC16(dst, src) \
    asm volatile("cp.async.cg.shared.global [%0], [%1], 16;" :: "r"(dst), "l"(src))
#define CP_COMMIT() asm volatile("cp.async.commit_group;" ::: "memory")
#define CP_WAIT2()  asm volatile("cp.async.wait_group 2;" ::: "memory")

__device__ __forceinline__ void ldsm_x4(uint32_t* r, uint32_t addr) {
    asm volatile("ldmatrix.sync.aligned.m8n8.x4.shared.b16 {%0,%1,%2,%3}, [%4];"
        : "=r"(r[0]), "=r"(r[1]), "=r"(r[2]), "=r"(r[3]) : "r"(addr));
}
__device__ __forceinline__ void mma_bf16(float* c, const uint32_t* a, const uint32_t* b) {
    asm volatile("mma.sync.aligned.m16n8k16.row.col.f32.bf16.bf16.f32 "
        "{%0,%1,%2,%3}, {%4,%5,%6,%7}, {%8,%9}, {%0,%1,%2,%3};"
        : "+f"(c[0]), "+f"(c[1]), "+f"(c[2]), "+f"(c[3])
        : "r"(a[0]), "r"(a[1]), "r"(a[2]), "r"(a[3]), "r"(b[0]), "r"(b[1]));
}

// ---------------- prep kernels ----------------
__device__ __forceinline__ void split2(float v, __nv_bfloat16& h, __nv_bfloat16& l) {
    h = __float2bfloat16(v);
    l = __float2bfloat16(v - __bfloat162float(h));
}

__global__ void split_kernel(const float* __restrict__ src,
                             __nv_bfloat16* __restrict__ h,
                             __nv_bfloat16* __restrict__ l, size_t n) {
    size_t i = (size_t)blockIdx.x * blockDim.x + threadIdx.x;
    size_t stride = (size_t)gridDim.x * blockDim.x;
    for (; i < n; i += stride) {
        __nv_bfloat16 hh, ll;
        split2(src[i], hh, ll);
        h[i] = hh; l[i] = ll;
    }
}

// W [Dd][Dd] -> Wt[n][k] = W[k][n], split hi/lo
__global__ void transpose_split_kernel(const float* __restrict__ W,
                                       __nv_bfloat16* __restrict__ th,
                                       __nv_bfloat16* __restrict__ tl) {
    __shared__ float tile[32][33];
    int bx = blockIdx.x * 32, by = blockIdx.y * 32;
    int tx = threadIdx.x, ty = threadIdx.y;
    #pragma unroll
    for (int j = 0; j < 4; j++)
        tile[ty + 8 * j][tx] = W[(size_t)(by + ty + 8 * j) * Dd + bx + tx];
    __syncthreads();
    #pragma unroll
    for (int j = 0; j < 4; j++) {
        float v = tile[tx][ty + 8 * j];
        __nv_bfloat16 hh, ll;
        split2(v, hh, ll);
        size_t o = (size_t)(bx + ty + 8 * j) * Dd + by + tx;
        th[o] = hh; tl[o] = ll;
    }
}

// causal softmax on S rows; writes split probs to ph/pl, zero-pads to 128-mult
__global__ __launch_bounds__(256)
void softmax_causal(float* __restrict__ Sm, __nv_bfloat16* __restrict__ ph,
                    __nv_bfloat16* __restrict__ pl) {
    const int gq = blockIdx.x;
    const int q  = gq & (Sq - 1);
    float* row = Sm + (size_t)gq * Sq;
    __nv_bfloat16* hrow = ph + (size_t)gq * Sq;
    __nv_bfloat16* lrow = pl + (size_t)gq * Sq;
    const int len = q + 1;
    const int tid = threadIdx.x;
    __shared__ float red[256];

    float m = -1e30f;
    for (int j = tid; j < len; j += 256) m = fmaxf(m, row[j]);
    red[tid] = m; __syncthreads();
    for (int s = 128; s > 0; s >>= 1) {
        if (tid < s) red[tid] = fmaxf(red[tid], red[tid + s]);
        __syncthreads();
    }
    m = red[0]; __syncthreads();

    float sum = 0.f;
    for (int j = tid; j < len; j += 256) {
        float e = __expf(row[j] - m);
        row[j] = e; sum += e;
    }
    red[tid] = sum; __syncthreads();
    for (int s = 128; s > 0; s >>= 1) {
        if (tid < s) red[tid] += red[tid + s];
        __syncthreads();
    }
    const float inv = 1.0f / red[0];

    for (int j = tid; j < len; j += 256) {
        __nv_bfloat16 hh, ll;
        split2(row[j] * inv, hh, ll);
        hrow[j] = hh; lrow[j] = ll;
    }
    const int jend = ((q >> 7) + 1) << 7;
    const __nv_bfloat16 z = __float2bfloat16(0.f);
    for (int j = len + tid; j < jend; j += 256) { hrow[j] = z; lrow[j] = z; }
}

// ---------------- HMMA NT GEMM (bf16x3) ----------------
// C[128,128] per CTA = Ah*Bh^T + Ah*Bl^T + Al*Bh^T, K-major operands.
#define ROWB 144                         // 64 bf16 = 128B data + 16B pad
#define TILE_SB (128 * ROWB)             // 18432 bytes
#define STAGE_B (4 * TILE_SB)            // 73728
#define NSTAGE 3
#define GEMM_SMEM (NSTAGE * STAGE_B)     // 221184
#define TAH 0
#define TAL TILE_SB
#define TBH (2 * TILE_SB)
#define TBL (3 * TILE_SB)

__device__ __forceinline__ void load_tile_async(uint32_t dst, const __nv_bfloat16* src,
                                                int ldK, int tid) {
    #pragma unroll
    for (int j = 0; j < 4; j++) {
        int s = tid + j * 256;
        int r = s >> 3, c = s & 7;
        CP_ASYNC16(dst + r * ROWB + c * 16, src + (size_t)r * ldK + c * 8);
    }
}

// epilogue modes: 0 = fp32 out (bias?, scale), 1 = split hi/lo (+bias?),
//                 2 = split transposed (V: vt[z2][n][m]) with bias
__global__ __launch_bounds__(256, 1)
void gemm_bf16x3(const __nv_bfloat16* __restrict__ Ah, const __nv_bfloat16* __restrict__ Al,
                 const __nv_bfloat16* __restrict__ Bh, const __nv_bfloat16* __restrict__ Bl,
                 int Kdim, long sAz, long sBz,
                 const float* __restrict__ bias,
                 float* __restrict__ outF,
                 __nv_bfloat16* __restrict__ outH, __nv_bfloat16* __restrict__ outL,
                 long sOz, int ldOut, float scale, int causal, int mode)
{
    const int bx = blockIdx.x, by = blockIdx.y, z = blockIdx.z;
    if (causal == 1 && bx > by) return;
    const int kend = (causal == 2) ? (by + 1) * 128 : Kdim;
    const int nchunk = kend >> 6;                 // BK = 64

    extern __shared__ __align__(16) char smem[];
    const uint32_t sb = smem_u32(smem);

    const int tid  = threadIdx.x;
    const int lane = tid & 31;
    const int wid  = tid >> 5;
    const int wm   = wid >> 2;                    // 0..1
    const int wn   = wid & 3;                     // 0..3

    const __nv_bfloat16* pAh = Ah + (size_t)z * sAz + (size_t)by * 128 * Kdim;
    const __nv_bfloat16* pAl = Al + (size_t)z * sAz + (size_t)by * 128 * Kdim;
    const __nv_bfloat16* pBh = Bh + (size_t)z * sBz + (size_t)bx * 128 * Kdim;
    const __nv_bfloat16* pBl = Bl + (size_t)z * sBz + (size_t)bx * 128 * Kdim;

    float acc[4][4][4] = {};

    // prologue: fill up to 3 stages
    #pragma unroll
    for (int p = 0; p < NSTAGE; p++) {
        if (p < nchunk) {
            const size_t ko = (size_t)p << 6;
            uint32_t st = sb + p * STAGE_B;
            load_tile_async(st + TAH, pAh + ko, Kdim, tid);
            load_tile_async(st + TAL, pAl + ko, Kdim, tid);
            load_tile_async(st + TBH, pBh + ko, Kdim, tid);
            load_tile_async(st + TBL, pBl + ko, Kdim, tid);
        }
        CP_COMMIT();
    }

    // ldmatrix lane address components
    const uint32_t arow = (lane & 7) + ((lane & 8)  ? 8 : 0);
    const uint32_t acol = (lane & 16) ? 16u : 0u;
    const uint32_t brow = (lane & 7) + ((lane & 16) ? 8 : 0);
    const uint32_t bcol = (lane & 8)  ? 16u : 0u;

    for (int c = 0; c < nchunk; ++c) {
        CP_WAIT2();
        __syncthreads();
        const uint32_t base = sb + (c % NSTAGE) * STAGE_B;

        #pragma unroll
        for (int ks = 0; ks < 4; ks++) {
            uint32_t ah[4][4], al[4][4], bh[4][2], bl[4][2];
            const uint32_t kb = ks * 32;
            #pragma unroll
            for (int i = 0; i < 4; i++) {
                uint32_t off = (wm * 64 + i * 16 + arow) * ROWB + kb + acol;
                ldsm_x4(ah[i], base + TAH + off);
                ldsm_x4(al[i], base + TAL + off);
            }
            #pragma unroll
            for (int j2 = 0; j2 < 2; j2++) {
                uint32_t off = (wn * 32 + j2 * 16 + brow) * ROWB + kb + bcol;
                uint32_t t[4];
                ldsm_x4(t, base + TBH + off);
                bh[j2 * 2][0] = t[0]; bh[j2 * 2][1] = t[1];
                bh[j2 * 2 + 1][0] = t[2]; bh[j2 * 2 + 1][1] = t[3];
                ldsm_x4(t, base + TBL + off);
                bl[j2 * 2][0] = t[0]; bl[j2 * 2][1] = t[1];
                bl[j2 * 2 + 1][0] = t[2]; bl[j2 * 2 + 1][1] = t[3];
            }
            #pragma unroll
            for (int i = 0; i < 4; i++)
                #pragma unroll
                for (int j = 0; j < 4; j++) {
                    mma_bf16(acc[i][j], ah[i], bh[j]);
                    mma_bf16(acc[i][j], ah[i], bl[j]);
                    mma_bf16(acc[i][j], al[i], bh[j]);
                }
        }

        __syncthreads();
        if (c + NSTAGE < nchunk) {
            const size_t ko = (size_t)(c + NSTAGE) << 6;
            uint32_t st = sb + (c % NSTAGE) * STAGE_B;
            load_tile_async(st + TAH, pAh + ko, Kdim, tid);
            load_tile_async(st + TAL, pAl + ko, Kdim, tid);
            load_tile_async(st + TBH, pBh + ko, Kdim, tid);
            load_tile_async(st + TBL, pBl + ko, Kdim, tid);
        }
        CP_COMMIT();
    }

    // ---------------- epilogue ----------------
    const int m_base = by * 128 + wm * 64;
    const int n_base = bx * 128 + wn * 32;
    const int rr = lane >> 2;
    const int cc = 2 * (lane & 3);

    #pragma unroll
    for (int i = 0; i < 4; i++) {
        #pragma unroll
        for (int j = 0; j < 4; j++) {
            const int col = n_base + j * 8 + cc;
            #pragma unroll
            for (int h = 0; h < 2; h++) {
                const int row = m_base + i * 16 + rr + h * 8;
                float v0 = acc[i][j][2 * h + 0];
                float v1 = acc[i][j][2 * h + 1];
                if (mode == 0) {
                    v0 *= scale; v1 *= scale;
                    if (bias) { v0 += __ldg(&bias[col]); v1 += __ldg(&bias[col + 1]); }
                    float2 o = make_float2(v0, v1);
                    *(float2*)(outF + (size_t)z * sOz + (size_t)row * ldOut + col) = o;
                } else if (mode == 1) {
                    if (bias) { v0 += __ldg(&bias[col]); v1 += __ldg(&bias[col + 1]); }
                    __nv_bfloat16 h0, l0, h1, l1;
                    split2(v0, h0, l0); split2(v1, h1, l1);
                    size_t o = (size_t)z * sOz + (size_t)row * ldOut + col;
                    *(__nv_bfloat162*)(outH + o) = __nv_bfloat162(h0, h1);
                    *(__nv_bfloat162*)(outL + o) = __nv_bfloat162(l0, l1);
                } else {
                    if (bias) { v0 += __ldg(&bias[col]); v1 += __ldg(&bias[col + 1]); }
                    const long z2 = row >> 11;
                    const long mloc = row & (Sq - 1);
                    __nv_bfloat16 h0, l0, h1, l1;
                    split2(v0, h0, l0); split2(v1, h1, l1);
                    size_t o0 = ((size_t)z2 * Dd + col) * Sq + mloc;
                    size_t o1 = ((size_t)z2 * Dd + col + 1) * Sq + mloc;
                    outH[o0] = h0; outL[o0] = l0;
                    outH[o1] = h1; outL[o1] = l1;
                }
            }
        }
    }
}

// ---------------- launch ----------------
extern "C" void kernel_launch(void* const* d_in, const int* in_sizes, int n_in,
                              void* d_out, int out_size)
{
    const float* x  = (const float*)d_in[0];
    const float* Wq = (const float*)d_in[1];
    const float* bq = (const float*)d_in[2];
    const float* Wk = (const float*)d_in[3];
    const float* bk = (const float*)d_in[4];
    const float* Wv = (const float*)d_in[5];
    const float* bv = (const float*)d_in[6];
    const float* Wo = (const float*)d_in[7];
    const float* bo = (const float*)d_in[8];
    float* out = (float*)d_out;

    __nv_bfloat16 *xh, *xl, *wqh, *wql, *wkh, *wkl, *wvh, *wvl, *woh, *wol;
    __nv_bfloat16 *qh, *ql, *kh, *kl, *vth, *vtl, *phv, *plv, *aoh, *aol;
    float* Sp;
    cudaGetSymbolAddress((void**)&xh,  g_xh);   cudaGetSymbolAddress((void**)&xl,  g_xl);
    cudaGetSymbolAddress((void**)&wqh, g_wqh);  cudaGetSymbolAddress((void**)&wql, g_wql);
    cudaGetSymbolAddress((void**)&wkh, g_wkh);  cudaGetSymbolAddress((void**)&wkl, g_wkl);
    cudaGetSymbolAddress((void**)&wvh, g_wvh);  cudaGetSymbolAddress((void**)&wvl, g_wvl);
    cudaGetSymbolAddress((void**)&woh, g_woh);  cudaGetSymbolAddress((void**)&wol, g_wol);
    cudaGetSymbolAddress((void**)&qh,  g_qh);   cudaGetSymbolAddress((void**)&ql,  g_ql);
    cudaGetSymbolAddress((void**)&kh,  g_kh);   cudaGetSymbolAddress((void**)&kl,  g_kl);
    cudaGetSymbolAddress((void**)&vth, g_vth);  cudaGetSymbolAddress((void**)&vtl, g_vtl);
    cudaGetSymbolAddress((void**)&phv, g_ph);   cudaGetSymbolAddress((void**)&plv, g_pl);
    cudaGetSymbolAddress((void**)&aoh, g_aoh);  cudaGetSymbolAddress((void**)&aol, g_aol);
    cudaGetSymbolAddress((void**)&Sp,  g_S);

    cudaFuncSetAttribute(gemm_bf16x3, cudaFuncAttributeMaxDynamicSharedMemorySize, GEMM_SMEM);

    // prep: splits + weight transposes
    split_kernel<<<4096, 256>>>(x, xh, xl, (size_t)Mm * Dd);
    dim3 tb(32, 8), tg(Dd / 32, Dd / 32);
    transpose_split_kernel<<<tg, tb>>>(Wq, wqh, wql);
    transpose_split_kernel<<<tg, tb>>>(Wk, wkh, wkl);
    transpose_split_kernel<<<tg, tb>>>(Wv, wvh, wvl);
    transpose_split_kernel<<<tg, tb>>>(Wo, woh, wol);

    const float scale = 1.0f / 32.0f;

    // Q/K/V projections: M=8192, N=1024, K=1024
    dim3 gProj(Dd / 128, Mm / 128, 1);
    gemm_bf16x3<<<gProj, 256, GEMM_SMEM>>>(xh, xl, wqh, wql, Dd, 0, 0, bq,
        nullptr, qh, ql, 0, Dd, 1.f, 0, 1);
    gemm_bf16x3<<<gProj, 256, GEMM_SMEM>>>(xh, xl, wkh, wkl, Dd, 0, 0, bk,
        nullptr, kh, kl, 0, Dd, 1.f, 0, 1);
    gemm_bf16x3<<<gProj, 256, GEMM_SMEM>>>(xh, xl, wvh, wvl, Dd, 0, 0, bv,
        nullptr, vth, vtl, 0, Dd, 1.f, 0, 2);

    // scores: per-batch 2048x2048, K=1024, causal block skip, *1/32
    dim3 gSc(Sq / 128, Sq / 128, Bn);
    gemm_bf16x3<<<gSc, 256, GEMM_SMEM>>>(qh, ql, kh, kl, Dd,
        (long)Sq * Dd, (long)Sq * Dd, nullptr,
        Sp, nullptr, nullptr, (long)Sq * Sq, Sq, scale, 1, 0);

    softmax_causal<<<Mm, 256>>>(Sp, phv, plv);

    // PV: per-batch 2048x1024, K=2048 causally bounded
    dim3 gPV(Dd / 128, Sq / 128, Bn);
    gemm_bf16x3<<<gPV, 256, GEMM_SMEM>>>(phv, plv, vth, vtl, Sq,
        (long)Sq * Sq, (long)Dd * Sq, nullptr,
        nullptr, aoh, aol, (long)Sq * Dd, Dd, 1.f, 2, 1);

    // out projection: M=8192, N=1024, K=1024, fp32 out + bias
    gemm_bf16x3<<<gProj, 256, GEMM_SMEM>>>(aoh, aol, woh, wol, Dd, 0, 0, bo,
        out, nullptr, nullptr, 0, Dd, 1.f, 0, 0);
}

// round 4
// speedup vs baseline: 3.3737x; 1.1449x over previous
#include <cuda_runtime.h>
#include <cuda_bf16.h>
#include <cstdint>

// SingleSelfHeadAttention b=4, s=2048, d=1024, causal, fp32 I/O.
// GEMMs via mma.sync.m16n8k16 bf16 (HMMA), bf16x3 hi/lo emulated fp32.
// R4: 128x256 CTA tile, 64x64 warp tile, XOR-swizzled SMEM, 2-stage cp.async.

static constexpr int Bn = 4;
static constexpr int Sq = 2048;
static constexpr int Dd = 1024;
static constexpr int Mm = Bn * Sq;          // 8192

// ---------------- device scratch ----------------
__device__ __nv_bfloat16 g_xh[(size_t)Mm * Dd],  g_xl[(size_t)Mm * Dd];
__device__ __nv_bfloat16 g_wqh[(size_t)Dd * Dd], g_wql[(size_t)Dd * Dd];
__device__ __nv_bfloat16 g_wkh[(size_t)Dd * Dd], g_wkl[(size_t)Dd * Dd];
__device__ __nv_bfloat16 g_wvh[(size_t)Dd * Dd], g_wvl[(size_t)Dd * Dd];
__device__ __nv_bfloat16 g_woh[(size_t)Dd * Dd], g_wol[(size_t)Dd * Dd];
__device__ __nv_bfloat16 g_qh[(size_t)Mm * Dd],  g_ql[(size_t)Mm * Dd];
__device__ __nv_bfloat16 g_kh[(size_t)Mm * Dd],  g_kl[(size_t)Mm * Dd];
__device__ __nv_bfloat16 g_vth[(size_t)Bn * Dd * Sq], g_vtl[(size_t)Bn * Dd * Sq];
__device__ float         g_S [(size_t)Bn * Sq * Sq];
__device__ __nv_bfloat16 g_ph[(size_t)Bn * Sq * Sq], g_pl[(size_t)Bn * Sq * Sq];
__device__ __nv_bfloat16 g_aoh[(size_t)Mm * Dd], g_aol[(size_t)Mm * Dd];

// ---------------- PTX helpers ----------------
__device__ __forceinline__ uint32_t smem_u32(const void* p) {
    uint32_t a;
    asm("{ .reg .u64 t; cvta.to.shared.u64 t, %1; cvt.u32.u64 %0, t; }" : "=r"(a) : "l"(p));
    return a;
}
#define CP_ASYNC16(dst, src) \
    asm volatile("cp.async.cg.shared.global [%0], [%1], 16;" :: "r"(dst), "l"(src))
#define CP_COMMIT() asm volatile("cp.async.commit_group;" ::: "memory")
#define CP_WAIT1()  asm volatile("cp.async.wait_group 1;" ::: "memory")

__device__ __forceinline__ void ldsm_x4(uint32_t* r, uint32_t addr) {
    asm volatile("ldmatrix.sync.aligned.m8n8.x4.shared.b16 {%0,%1,%2,%3}, [%4];"
        : "=r"(r[0]), "=r"(r[1]), "=r"(r[2]), "=r"(r[3]) : "r"(addr));
}
__device__ __forceinline__ void mma_bf16(float* c, const uint32_t* a, const uint32_t* b) {
    asm volatile("mma.sync.aligned.m16n8k16.row.col.f32.bf16.bf16.f32 "
        "{%0,%1,%2,%3}, {%4,%5,%6,%7}, {%8,%9}, {%0,%1,%2,%3};"
        : "+f"(c[0]), "+f"(c[1]), "+f"(c[2]), "+f"(c[3])
        : "r"(a[0]), "r"(a[1]), "r"(a[2]), "r"(a[3]), "r"(b[0]), "r"(b[1]));
}
__device__ __forceinline__ uint32_t swz(uint32_t off) {   // 128B-row XOR swizzle
    return off ^ ((off >> 3) & 0x70);
}

// ---------------- prep kernels ----------------
__device__ __forceinline__ void split2(float v, __nv_bfloat16& h, __nv_bfloat16& l) {
    h = __float2bfloat16(v);
    l = __float2bfloat16(v - __bfloat162float(h));
}

__global__ void split_kernel(const float* __restrict__ src,
                             __nv_bfloat16* __restrict__ h,
                             __nv_bfloat16* __restrict__ l, size_t n) {
    size_t i = (size_t)blockIdx.x * blockDim.x + threadIdx.x;
    size_t stride = (size_t)gridDim.x * blockDim.x;
    for (; i < n; i += stride) {
        __nv_bfloat16 hh, ll;
        split2(src[i], hh, ll);
        h[i] = hh; l[i] = ll;
    }
}

// W [Dd][Dd] -> Wt[n][k] = W[k][n], split hi/lo
__global__ void transpose_split_kernel(const float* __restrict__ W,
                                       __nv_bfloat16* __restrict__ th,
                                       __nv_bfloat16* __restrict__ tl) {
    __shared__ float tile[32][33];
    int bx = blockIdx.x * 32, by = blockIdx.y * 32;
    int tx = threadIdx.x, ty = threadIdx.y;
    #pragma unroll
    for (int j = 0; j < 4; j++)
        tile[ty + 8 * j][tx] = W[(size_t)(by + ty + 8 * j) * Dd + bx + tx];
    __syncthreads();
    #pragma unroll
    for (int j = 0; j < 4; j++) {
        float v = tile[tx][ty + 8 * j];
        __nv_bfloat16 hh, ll;
        split2(v, hh, ll);
        size_t o = (size_t)(bx + ty + 8 * j) * Dd + by + tx;
        th[o] = hh; tl[o] = ll;
    }
}

// causal softmax on S rows; writes split probs to ph/pl, zero-pads to 128-mult
__global__ __launch_bounds__(256)
void softmax_causal(float* __restrict__ Sm, __nv_bfloat16* __restrict__ ph,
                    __nv_bfloat16* __restrict__ pl) {
    const int gq = blockIdx.x;
    const int q  = gq & (Sq - 1);
    float* row = Sm + (size_t)gq * Sq;
    __nv_bfloat16* hrow = ph + (size_t)gq * Sq;
    __nv_bfloat16* lrow = pl + (size_t)gq * Sq;
    const int len = q + 1;
    const int tid = threadIdx.x;
    __shared__ float red[256];

    float m = -1e30f;
    for (int j = tid; j < len; j += 256) m = fmaxf(m, row[j]);
    red[tid] = m; __syncthreads();
    for (int s = 128; s > 0; s >>= 1) {
        if (tid < s) red[tid] = fmaxf(red[tid], red[tid + s]);
        __syncthreads();
    }
    m = red[0]; __syncthreads();

    float sum = 0.f;
    for (int j = tid; j < len; j += 256) {
        float e = __expf(row[j] - m);
        row[j] = e; sum += e;
    }
    red[tid] = sum; __syncthreads();
    for (int s = 128; s > 0; s >>= 1) {
        if (tid < s) red[tid] += red[tid + s];
        __syncthreads();
    }
    const float inv = 1.0f / red[0];

    for (int j = tid; j < len; j += 256) {
        __nv_bfloat16 hh, ll;
        split2(row[j] * inv, hh, ll);
        hrow[j] = hh; lrow[j] = ll;
    }
    const int jend = ((q >> 7) + 1) << 7;
    const __nv_bfloat16 z = __float2bfloat16(0.f);
    for (int j = len + tid; j < jend; j += 256) { hrow[j] = z; lrow[j] = z; }
}

// ---------------- HMMA NT GEMM (bf16x3), 128x256 CTA tile ----------------
// C = Ah*Bh^T + Ah*Bl^T + Al*Bh^T, K-major operands, BK=64.
#define TM_CTA 128
#define TN_CTA 256
#define A_TILE (TM_CTA * 128)            // 16384 B (128 rows x 128B)
#define B_TILE (TN_CTA * 128)            // 32768 B
#define TAH 0
#define TAL (A_TILE)
#define TBH (2 * A_TILE)
#define TBL (2 * A_TILE + B_TILE)
#define STAGE_B (2 * A_TILE + 2 * B_TILE) // 98304
#define NSTAGE 2
#define GEMM_SMEM (NSTAGE * STAGE_B)      // 196608

__device__ __forceinline__ void load_A_async(uint32_t dst, const __nv_bfloat16* src,
                                             int ldK, int tid) {
    #pragma unroll
    for (int j = 0; j < 4; j++) {                 // 128 rows x 8 chunks / 256 thr
        int s = tid + j * 256;
        int r = s >> 3, c = s & 7;
        CP_ASYNC16(dst + swz(r * 128 + c * 16), src + (size_t)r * ldK + c * 8);
    }
}
__device__ __forceinline__ void load_B_async(uint32_t dst, const __nv_bfloat16* src,
                                             int ldK, int tid) {
    #pragma unroll
    for (int j = 0; j < 8; j++) {                 // 256 rows x 8 chunks / 256 thr
        int s = tid + j * 256;
        int r = s >> 3, c = s & 7;
        CP_ASYNC16(dst + swz(r * 128 + c * 16), src + (size_t)r * ldK + c * 8);
    }
}

// epilogue modes: 0 = fp32 out (bias?, scale), 1 = split hi/lo (+bias?),
//                 2 = split transposed (V: vt[z2][n][m]) with bias
__global__ __launch_bounds__(256, 1)
void gemm_bf16x3(const __nv_bfloat16* __restrict__ Ah, const __nv_bfloat16* __restrict__ Al,
                 const __nv_bfloat16* __restrict__ Bh, const __nv_bfloat16* __restrict__ Bl,
                 int Kdim, long sAz, long sBz,
                 const float* __restrict__ bias,
                 float* __restrict__ outF,
                 __nv_bfloat16* __restrict__ outH, __nv_bfloat16* __restrict__ outL,
                 long sOz, int ldOut, float scale, int causal, int mode)
{
    const int bx = blockIdx.x, by = blockIdx.y, z = blockIdx.z;
    if (causal == 1 && 2 * bx > by) return;       // 256-wide col tile above diag
    const int kend = (causal == 2) ? (by + 1) * 128 : Kdim;
    const int nchunk = kend >> 6;                 // BK = 64

    extern __shared__ __align__(16) char smem[];
    const uint32_t sb = smem_u32(smem);

    const int tid  = threadIdx.x;
    const int lane = tid & 31;
    const int wid  = tid >> 5;
    const int wm   = wid >> 2;                    // 0..1 (64-row block)
    const int wn   = wid & 3;                     // 0..3 (64-col block)

    const __nv_bfloat16* pAh = Ah + (size_t)z * sAz + (size_t)by * TM_CTA * Kdim;
    const __nv_bfloat16* pAl = Al + (size_t)z * sAz + (size_t)by * TM_CTA * Kdim;
    const __nv_bfloat16* pBh = Bh + (size_t)z * sBz + (size_t)bx * TN_CTA * Kdim;
    const __nv_bfloat16* pBl = Bl + (size_t)z * sBz + (size_t)bx * TN_CTA * Kdim;

    float acc[4][8][4] = {};

    #pragma unroll
    for (int p = 0; p < NSTAGE; p++) {
        if (p < nchunk) {
            const size_t ko = (size_t)p << 6;
            uint32_t st = sb + p * STAGE_B;
            load_A_async(st + TAH, pAh + ko, Kdim, tid);
            load_A_async(st + TAL, pAl + ko, Kdim, tid);
            load_B_async(st + TBH, pBh + ko, Kdim, tid);
            load_B_async(st + TBL, pBl + ko, Kdim, tid);
        }
        CP_COMMIT();
    }

    // ldmatrix lane address components
    const uint32_t arow = (lane & 7) + ((lane & 8)  ? 8 : 0);
    const uint32_t acol = (lane & 16) ? 16u : 0u;
    const uint32_t brow = (lane & 7) + ((lane & 16) ? 8 : 0);
    const uint32_t bcol = (lane & 8)  ? 16u : 0u;

    for (int c = 0; c < nchunk; ++c) {
        CP_WAIT1();
        __syncthreads();
        const uint32_t base = sb + (c & 1) * STAGE_B;

        #pragma unroll
        for (int ks = 0; ks < 4; ks++) {
            const uint32_t kb = ks * 32;
            uint32_t ah[4][4], al[4][4];
            #pragma unroll
            for (int i = 0; i < 4; i++) {
                uint32_t off = swz((wm * 64 + i * 16 + arow) * 128 + kb + acol);
                ldsm_x4(ah[i], base + TAH + off);
                ldsm_x4(al[i], base + TAL + off);
            }
            #pragma unroll
            for (int j2 = 0; j2 < 4; j2++) {
                uint32_t off = swz((wn * 64 + j2 * 16 + brow) * 128 + kb + bcol);
                uint32_t th[4], tl[4];
                ldsm_x4(th, base + TBH + off);
                ldsm_x4(tl, base + TBL + off);
                const int j0 = j2 * 2, j1 = j2 * 2 + 1;
                #pragma unroll
                for (int i = 0; i < 4; i++) {
                    mma_bf16(acc[i][j0], ah[i], &th[0]);
                    mma_bf16(acc[i][j1], ah[i], &th[2]);
                    mma_bf16(acc[i][j0], ah[i], &tl[0]);
                    mma_bf16(acc[i][j1], ah[i], &tl[2]);
                    mma_bf16(acc[i][j0], al[i], &th[0]);
                    mma_bf16(acc[i][j1], al[i], &th[2]);
                }
            }
        }

        __syncthreads();
        if (c + NSTAGE < nchunk) {
            const size_t ko = (size_t)(c + NSTAGE) << 6;
            uint32_t st = sb + (c & 1) * STAGE_B;
            load_A_async(st + TAH, pAh + ko, Kdim, tid);
            load_A_async(st + TAL, pAl + ko, Kdim, tid);
            load_B_async(st + TBH, pBh + ko, Kdim, tid);
            load_B_async(st + TBL, pBl + ko, Kdim, tid);
        }
        CP_COMMIT();
    }

    // ---------------- epilogue ----------------
    const int m_base = by * TM_CTA + wm * 64;
    const int n_base = bx * TN_CTA + wn * 64;
    const int rr = lane >> 2;
    const int cc = 2 * (lane & 3);

    #pragma unroll
    for (int i = 0; i < 4; i++) {
        #pragma unroll
        for (int j = 0; j < 8; j++) {
            const int col = n_base + j * 8 + cc;
            #pragma unroll
            for (int h = 0; h < 2; h++) {
                const int row = m_base + i * 16 + rr + h * 8;
                float v0 = acc[i][j][2 * h + 0];
                float v1 = acc[i][j][2 * h + 1];
                if (mode == 0) {
                    v0 *= scale; v1 *= scale;
                    if (bias) { v0 += __ldg(&bias[col]); v1 += __ldg(&bias[col + 1]); }
                    float2 o = make_float2(v0, v1);
                    *(float2*)(outF + (size_t)z * sOz + (size_t)row * ldOut + col) = o;
                } else if (mode == 1) {
                    if (bias) { v0 += __ldg(&bias[col]); v1 += __ldg(&bias[col + 1]); }
                    __nv_bfloat16 h0, l0, h1, l1;
                    split2(v0, h0, l0); split2(v1, h1, l1);
                    size_t o = (size_t)z * sOz + (size_t)row * ldOut + col;
                    *(__nv_bfloat162*)(outH + o) = __nv_bfloat162(h0, h1);
                    *(__nv_bfloat162*)(outL + o) = __nv_bfloat162(l0, l1);
                } else {
                    if (bias) { v0 += __ldg(&bias[col]); v1 += __ldg(&bias[col + 1]); }
                    const long z2 = row >> 11;
                    const long mloc = row & (Sq - 1);
                    __nv_bfloat16 h0, l0, h1, l1;
                    split2(v0, h0, l0); split2(v1, h1, l1);
                    size_t o0 = ((size_t)z2 * Dd + col) * Sq + mloc;
                    size_t o1 = ((size_t)z2 * Dd + col + 1) * Sq + mloc;
                    outH[o0] = h0; outL[o0] = l0;
                    outH[o1] = h1; outL[o1] = l1;
                }
            }
        }
    }
}

// ---------------- launch ----------------
extern "C" void kernel_launch(void* const* d_in, const int* in_sizes, int n_in,
                              void* d_out, int out_size)
{
    const float* x  = (const float*)d_in[0];
    const float* Wq = (const float*)d_in[1];
    const float* bq = (const float*)d_in[2];
    const float* Wk = (const float*)d_in[3];
    const float* bk = (const float*)d_in[4];
    const float* Wv = (const float*)d_in[5];
    const float* bv = (const float*)d_in[6];
    const float* Wo = (const float*)d_in[7];
    const float* bo = (const float*)d_in[8];
    float* out = (float*)d_out;

    __nv_bfloat16 *xh, *xl, *wqh, *wql, *wkh, *wkl, *wvh, *wvl, *woh, *wol;
    __nv_bfloat16 *qh, *ql, *kh, *kl, *vth, *vtl, *phv, *plv, *aoh, *aol;
    float* Sp;
    cudaGetSymbolAddress((void**)&xh,  g_xh);   cudaGetSymbolAddress((void**)&xl,  g_xl);
    cudaGetSymbolAddress((void**)&wqh, g_wqh);  cudaGetSymbolAddress((void**)&wql, g_wql);
    cudaGetSymbolAddress((void**)&wkh, g_wkh);  cudaGetSymbolAddress((void**)&wkl, g_wkl);
    cudaGetSymbolAddress((void**)&wvh, g_wvh);  cudaGetSymbolAddress((void**)&wvl, g_wvl);
    cudaGetSymbolAddress((void**)&woh, g_woh);  cudaGetSymbolAddress((void**)&wol, g_wol);
    cudaGetSymbolAddress((void**)&qh,  g_qh);   cudaGetSymbolAddress((void**)&ql,  g_ql);
    cudaGetSymbolAddress((void**)&kh,  g_kh);   cudaGetSymbolAddress((void**)&kl,  g_kl);
    cudaGetSymbolAddress((void**)&vth, g_vth);  cudaGetSymbolAddress((void**)&vtl, g_vtl);
    cudaGetSymbolAddress((void**)&phv, g_ph);   cudaGetSymbolAddress((void**)&plv, g_pl);
    cudaGetSymbolAddress((void**)&aoh, g_aoh);  cudaGetSymbolAddress((void**)&aol, g_aol);
    cudaGetSymbolAddress((void**)&Sp,  g_S);

    cudaFuncSetAttribute(gemm_bf16x3, cudaFuncAttributeMaxDynamicSharedMemorySize, GEMM_SMEM);

    // prep: splits + weight transposes
    split_kernel<<<4096, 256>>>(x, xh, xl, (size_t)Mm * Dd);
    dim3 tb(32, 8), tg(Dd / 32, Dd / 32);
    transpose_split_kernel<<<tg, tb>>>(Wq, wqh, wql);
    transpose_split_kernel<<<tg, tb>>>(Wk, wkh, wkl);
    transpose_split_kernel<<<tg, tb>>>(Wv, wvh, wvl);
    transpose_split_kernel<<<tg, tb>>>(Wo, woh, wol);

    const float scale = 1.0f / 32.0f;

    // Q/K/V projections: M=8192, N=1024, K=1024
    dim3 gProj(Dd / TN_CTA, Mm / TM_CTA, 1);      // 4 x 64
    gemm_bf16x3<<<gProj, 256, GEMM_SMEM>>>(xh, xl, wqh, wql, Dd, 0, 0, bq,
        nullptr, qh, ql, 0, Dd, 1.f, 0, 1);
    gemm_bf16x3<<<gProj, 256, GEMM_SMEM>>>(xh, xl, wkh, wkl, Dd, 0, 0, bk,
        nullptr, kh, kl, 0, Dd, 1.f, 0, 1);
    gemm_bf16x3<<<gProj, 256, GEMM_SMEM>>>(xh, xl, wvh, wvl, Dd, 0, 0, bv,
        nullptr, vth, vtl, 0, Dd, 1.f, 0, 2);

    // scores: per-batch 2048x2048, K=1024, causal block skip, *1/32
    dim3 gSc(Sq / TN_CTA, Sq / TM_CTA, Bn);       // 8 x 16 x 4
    gemm_bf16x3<<<gSc, 256, GEMM_SMEM>>>(qh, ql, kh, kl, Dd,
        (long)Sq * Dd, (long)Sq * Dd, nullptr,
        Sp, nullptr, nullptr, (long)Sq * Sq, Sq, scale, 1, 0);

    softmax_causal<<<Mm, 256>>>(Sp, phv, plv);

    // PV: per-batch 2048x1024, K=2048 causally bounded
    dim3 gPV(Dd / TN_CTA, Sq / TM_CTA, Bn);       // 4 x 16 x 4
    gemm_bf16x3<<<gPV, 256, GEMM_SMEM>>>(phv, plv, vth, vtl, Sq,
        (long)Sq * Sq, (long)Dd * Sq, nullptr,
        nullptr, aoh, aol, (long)Sq * Dd, Dd, 1.f, 2, 1);

    // out projection: M=8192, N=1024, K=1024, fp32 out + bias
    gemm_bf16x3<<<gProj, 256, GEMM_SMEM>>>(aoh, aol, woh, wol, Dd, 0, 0, bo,
        out, nullptr, nullptr, 0, Dd, 1.f, 0, 0);
}